// round 16
// baseline (speedup 1.0000x reference)
#include <cuda_runtime.h>

// HMM forward: alpha_{t+1} = (alpha_t @ A) * Bo[t],  answer = sum(alpha_{T-1})
//
// R16 = R15 (best 4774us: fused kernel, tier-interleaved KR40/KS52/KT36,
// L2 prefetch ring depth 9, cp.async staging, single-counter barrier; math
// bit-identical to R1, rel_err 9.477166e-4) + PROGRESSIVE staging:
//   alpha staged as 4 cp.async commit-groups (1 per 1024-float period);
//   compute period p after cp.async.wait_group (3-p) + bar.sync, so periods
//   1..3 of the staging latency hide behind periods 0..2 of compute.
// Consumption order k=0..127 and all values unchanged -> bit-identical.

#define N_STATES 4096
#define SEQ_T    1024
#define N_OBS    128
#define NCTA     128
#define NTHR     256
#define COLS_PER_CTA 32

#define KR 40                        // 4 periods x 10
#define KS 52                        // 4 periods x 13
#define KT 36                        // 4 periods x 9
#define S_ROWS (KS * 32)             // 1664
#define S_PITCH (S_ROWS + 1)         // 1665
#define T3_ROWS (KT * 32)            // 1152

// dynamic smem: sA[8][S_PITCH] float4 (213,120B) + s_alpha[4096] f32 = 229,504B
#define SMEM_BYTES (8 * S_PITCH * 16 + N_STATES * 4)

typedef unsigned long long ull;

__device__ float    g_Bo[SEQ_T * N_STATES];
__device__ float4   g_A3T[1024 * T3_ROWS];     // [cg_global][slot*32 + lane]
__device__ float    g_alpha[2][N_STATES];
__device__ unsigned g_count;
__device__ unsigned g_sense;   // even #flips per launch -> restored

// ---------------------------------------------------------------------------
// Single-counter sense-reversing grid barrier (R5/R12-proven).
__device__ __forceinline__ void grid_barrier(unsigned& local_sense, unsigned nblocks) {
    __syncthreads();
    if (threadIdx.x == 0) {
        unsigned s = local_sense ^ 1u;
        local_sense = s;
        __threadfence();
        if (atomicAdd(&g_count, 1u) == nblocks - 1u) {
            g_count = 0u;
            __threadfence();
            atomicExch(&g_sense, s);
        } else {
            while (*(volatile unsigned*)&g_sense != s) { }
        }
        __threadfence();
    }
    __syncthreads();
}

// packed f32x2 fma: component-wise IEEE fp32 fma (bit-identical to scalar)
__device__ __forceinline__ void fma2(ull& d, ull v, ull a) {
    asm("fma.rn.f32x2 %0, %1, %2, %0;" : "+l"(d) : "l"(v), "l"(a));
}
__device__ __forceinline__ ull pack2(float a) {
    ull r;
    asm("mov.b64 %0, {%1, %2};" : "=l"(r) : "f"(a), "f"(a));
    return r;
}
__device__ __forceinline__ unsigned smem_u32(const void* p) {
    unsigned a;
    asm("{ .reg .u64 t; cvta.to.shared.u64 t, %1; cvt.u32.u64 %0, t; }"
        : "=r"(a) : "l"(p));
    return a;
}

// one 32-slot period of the dot-product chain (k = 32*P + r, r ascending)
#define PERIOD(P)                                                             \
    _Pragma("unroll")                                                         \
    for (int r = 0; r < 32; ++r) {                                            \
        int k = 32 * (P) + r;                                                 \
        ull aa = pack2(s_alpha[lane + 32 * k]);                               \
        ulonglong2 v;                                                         \
        if (r % 3 == 0 && r <= 27) {                                          \
            v = rA[(P) * 10 + r / 3];                                         \
        } else if (r % 3 == 2 && r <= 26) {                                   \
            int s = (r - 2) / 3;                                              \
            v = pf[s];                                                        \
            pf[s] = A3w[(((((P) + 1) & 3)) * 9 + s) * 32 + lane];             \
        } else {                                                              \
            int m = (r % 3 == 1) ? (r - 1) / 3 : (r == 29 ? 11 : 12);         \
            v = sAw[((P) * 13 + m) * 32 + lane];                              \
        }                                                                     \
        fma2(acc01, v.x, aa);                                                 \
        fma2(acc23, v.y, aa);                                                 \
    }

// ---------------------------------------------------------------------------
__global__ void __launch_bounds__(NTHR, 1)
hmm_forward_kernel(const float* __restrict__ A,
                   const float* __restrict__ B,
                   const int*   __restrict__ obs_raw,
                   const float* __restrict__ pi,
                   float*       __restrict__ out) {
    extern __shared__ float smem[];
    float4* sA      = reinterpret_cast<float4*>(smem);        // [8][S_PITCH]
    float*  s_alpha = smem + 8 * S_PITCH * 4;                 // 4096 floats

    const int tid  = threadIdx.x;
    const int cta  = blockIdx.x;
    const int lane = tid & 31;            // row slot
    const int cg   = tid >> 5;            // warp id = column group, 0..7
    const int gcg  = cta * 8 + cg;
    const int col0 = cta * COLS_PER_CTA;

    const float4*     __restrict__ A4  = reinterpret_cast<const float4*>(A);
    const ulonglong2* __restrict__ A4u = reinterpret_cast<const ulonglong2*>(A);
    const float4*     __restrict__ A4base = A4 + cta * 8;

    // ================= PROLOGUE (all before grid barrier #1) =================

    // obs element-width detect (int64 little-endian: odd dwords are 0)
    int any = 0;
    for (int k = 1 + 2 * tid; k < 1024; k += 2 * NTHR)
        any |= obs_raw[k];
    int is32 = __syncthreads_or(any);

    // A3T transpose: KT*32 = 1152 (slot, col-block) tile tasks over 128 CTAs
    {
        float4 (*tile)[33] = reinterpret_cast<float4(*)[33]>(smem); // scratch
        int tx = tid & 31, ty = tid >> 5;
        for (int task = cta; task < KT * 32; task += NCTA) {
            int s  = task % KT;                        // slot 0..35
            int cb = task / KT;                        // col block 0..31
            int kk = 32 * (s / 9) + (s % 9) * 3 + 2;   // L2 slots: r=3j+2
            int r0 = 32 * kk, c0 = cb * 32;
            #pragma unroll
            for (int p = 0; p < 4; ++p)
                tile[ty + 8 * p][tx] =
                    A4[(size_t)(r0 + ty + 8 * p) * 1024 + (c0 + tx)];
            __syncthreads();
            #pragma unroll
            for (int p = 0; p < 4; ++p)
                g_A3T[(size_t)(c0 + ty + 8 * p) * T3_ROWS + s * 32 + tx] =
                    tile[tx][ty + 8 * p];
            __syncthreads();
        }
    }

    // Bo gather: 8 timesteps per CTA
    for (int t = cta; t < SEQ_T; t += NCTA) {
        int o = is32 ? obs_raw[t] : obs_raw[2 * t];
        for (int j = tid; j < N_STATES; j += NTHR)
            g_Bo[t * N_STATES + j] = B[j * N_OBS + o];
    }

    // RF tier: k with (k%32)%3 == 0 && (k%32) <= 27  (40 slots)
    ulonglong2 rA[KR];
    #pragma unroll
    for (int k = 0; k < 128; ++k) {
        int r = k & 31, p = k >> 5;
        if (r % 3 == 0 && r <= 27)
            rA[p * 10 + r / 3] = A4u[(size_t)(lane + 32 * k) * 1024 + gcg];
    }

    // SMEM tier (52 slots), sA[cg][slot*32 + row']
    for (int idx = tid; idx < S_ROWS * 8; idx += NTHR) {
        int cgf = idx & 7;
        int rr  = idx >> 3;
        int s = rr >> 5, rp = rr & 31;
        int m = s % 13, p = s / 13;
        int kk = 32 * p + ((m <= 10) ? 3 * m + 1 : (m == 11 ? 29 : 30));
        sA[cgf * S_PITCH + rr] = A4base[(size_t)(32 * kk + rp) * 1024 + cgf];
    }

    const ulonglong2* __restrict__ sAw =
        reinterpret_cast<const ulonglong2*>(sA + cg * S_PITCH);
    const ulonglong2* __restrict__ A3w =
        reinterpret_cast<const ulonglong2*>(g_A3T) + (size_t)gcg * T3_ROWS;

    // alpha0 = pi * Bo[0]
    if (tid < COLS_PER_CTA) {
        int j = col0 + tid;
        int o0 = is32 ? obs_raw[0] : obs_raw[0];
        g_alpha[0][j] = pi[j] * B[j * N_OBS + o0];
    }

    unsigned local_sense = 0;
    grid_barrier(local_sense, gridDim.x);          // barrier #1

    // prefetch ring: period 0's 9 L2 slots (static data, reused every step)
    ulonglong2 pf[9];
    #pragma unroll
    for (int s = 0; s < 9; ++s)
        pf[s] = A3w[s * 32 + lane];

    const unsigned s_alpha_addr = smem_u32(s_alpha);

    // ========================== MAIN SCAN LOOP ==========================
    int cur = 0;
    for (int t = 1; t < SEQ_T; ++t) {
        float4 bo;
        if (lane == 0)
            bo = reinterpret_cast<const float4*>(g_Bo + t * N_STATES)[gcg];

        // stage alpha as 4 commit-groups (group g = period g's 1024 floats)
        {
            const float4* asrc = reinterpret_cast<const float4*>(g_alpha[cur]);
            #pragma unroll
            for (int g = 0; g < 4; ++g) {
                unsigned d = s_alpha_addr + 16u * (tid + g * NTHR);
                asm volatile("cp.async.cg.shared.global [%0], [%1], 16;"
                             :: "r"(d), "l"(asrc + tid + g * NTHR) : "memory");
                asm volatile("cp.async.commit_group;" ::: "memory");
            }
        }

        // dot partials: i = lane + 32k, k ascending 0..127 (order contract);
        // period p computes after wait_group (3-p) + bar.sync.
        ull acc01 = 0ull, acc23 = 0ull;

        asm volatile("cp.async.wait_group 3;" ::: "memory");
        __syncthreads();
        PERIOD(0)
        asm volatile("cp.async.wait_group 2;" ::: "memory");
        __syncthreads();
        PERIOD(1)
        asm volatile("cp.async.wait_group 1;" ::: "memory");
        __syncthreads();
        PERIOD(2)
        asm volatile("cp.async.wait_group 0;" ::: "memory");
        __syncthreads();
        PERIOD(3)

        // unpack + xor butterfly (== R1's 32-slot tree at lane 0)
        float4 r4;
        asm("mov.b64 {%0, %1}, %2;" : "=f"(r4.x), "=f"(r4.y) : "l"(acc01));
        asm("mov.b64 {%0, %1}, %2;" : "=f"(r4.z), "=f"(r4.w) : "l"(acc23));
        #pragma unroll
        for (int m = 16; m > 0; m >>= 1) {
            r4.x += __shfl_xor_sync(0xffffffffu, r4.x, m);
            r4.y += __shfl_xor_sync(0xffffffffu, r4.y, m);
            r4.z += __shfl_xor_sync(0xffffffffu, r4.z, m);
            r4.w += __shfl_xor_sync(0xffffffffu, r4.w, m);
        }

        if (lane == 0) {
            float4 o4;
            o4.x = r4.x * bo.x; o4.y = r4.y * bo.y;
            o4.z = r4.z * bo.z; o4.w = r4.w * bo.w;
            reinterpret_cast<float4*>(g_alpha[cur ^ 1])[gcg] = o4;
        }

        grid_barrier(local_sense, gridDim.x);      // barriers #2..#1024 (even)
        cur ^= 1;
    }

    // ---- final sum (CTA 0): R1's exact 256-thread tree ----
    if (cta == 0) {
        float* sred = smem;
        float s = 0.f;
        for (int i = tid; i < N_STATES; i += NTHR)
            s += g_alpha[cur][i];
        sred[tid] = s;
        __syncthreads();
        #pragma unroll
        for (int k = NTHR / 2; k > 0; k >>= 1) {
            if (tid < k) sred[tid] += sred[tid + k];
            __syncthreads();
        }
        if (tid == 0) out[0] = sred[0];
    }
}

// ---------------------------------------------------------------------------
extern "C" void kernel_launch(void* const* d_in, const int* in_sizes, int n_in,
                              void* d_out, int out_size) {
    const float* A   = (const float*)d_in[0];
    const float* B   = (const float*)d_in[1];
    const float* pi  = (const float*)d_in[2];
    const int*   obs = (const int*)d_in[3];
    float* out = (float*)d_out;

    cudaFuncSetAttribute(hmm_forward_kernel,
                         cudaFuncAttributeMaxDynamicSharedMemorySize, SMEM_BYTES);

    hmm_forward_kernel<<<NCTA, NTHR, SMEM_BYTES>>>(A, B, obs, pi, out);
}

// round 17
// speedup vs baseline: 1.0349x; 1.0349x over previous
#include <cuda_runtime.h>

// HMM forward: alpha_{t+1} = (alpha_t @ A) * Bo[t],  answer = sum(alpha_{T-1})
//
// R17 = R12's tier split (KR44/KS52/KT32 — minimal L2 bytes: 16.8MB/step)
//     + R15's cp.async batched alpha staging (no RF round-trip, fewer
//       transient regs than LDG+STS, which is what let R12 sit at 255 regs).
// Everything else identical to the proven R12/R15 lineage: 128 CTA x 256 thr,
// warp-per-float4-group, tier-interleaved k-slots, L2 prefetch ring depth 8,
// single-counter grid barrier. Chain order k=0..127 and values unchanged ->
// bit-identical per-step alpha (rel_err 9.477166e-4).

#define N_STATES 4096
#define SEQ_T    1024
#define N_OBS    128
#define NCTA     128
#define NTHR     256
#define COLS_PER_CTA 32

#define KR 44                        // 4 periods x 11  (r%3==0)
#define KS 52                        // 4 periods x 13  (r%3==1, r==26, r==29)
#define KT 32                        // 4 periods x 8   (r%3==2 && r<=23)
#define S_ROWS (KS * 32)             // 1664
#define S_PITCH (S_ROWS + 1)         // 1665
#define T3_ROWS (KT * 32)            // 1024

// dynamic smem: sA[8][S_PITCH] float4 (213,120B) + s_alpha[4096] f32 = 229,504B
#define SMEM_BYTES (8 * S_PITCH * 16 + N_STATES * 4)

typedef unsigned long long ull;

__device__ float    g_Bo[SEQ_T * N_STATES];
__device__ float4   g_A3T[1024 * T3_ROWS];     // [cg_global][slot*32 + lane]
__device__ float    g_alpha[2][N_STATES];
__device__ unsigned g_count;
__device__ unsigned g_sense;   // even #flips per launch -> restored

// ---------------------------------------------------------------------------
// Single-counter sense-reversing grid barrier (R5/R12-proven).
__device__ __forceinline__ void grid_barrier(unsigned& local_sense, unsigned nblocks) {
    __syncthreads();
    if (threadIdx.x == 0) {
        unsigned s = local_sense ^ 1u;
        local_sense = s;
        __threadfence();
        if (atomicAdd(&g_count, 1u) == nblocks - 1u) {
            g_count = 0u;
            __threadfence();
            atomicExch(&g_sense, s);
        } else {
            while (*(volatile unsigned*)&g_sense != s) { }
        }
        __threadfence();
    }
    __syncthreads();
}

// packed f32x2 fma: component-wise IEEE fp32 fma (bit-identical to scalar)
__device__ __forceinline__ void fma2(ull& d, ull v, ull a) {
    asm("fma.rn.f32x2 %0, %1, %2, %0;" : "+l"(d) : "l"(v), "l"(a));
}
__device__ __forceinline__ ull pack2(float a) {
    ull r;
    asm("mov.b64 %0, {%1, %2};" : "=l"(r) : "f"(a), "f"(a));
    return r;
}
__device__ __forceinline__ unsigned smem_u32(const void* p) {
    unsigned a;
    asm("{ .reg .u64 t; cvta.to.shared.u64 t, %1; cvt.u32.u64 %0, t; }"
        : "=r"(a) : "l"(p));
    return a;
}

// ---------------------------------------------------------------------------
__global__ void __launch_bounds__(NTHR, 1)
hmm_forward_kernel(const float* __restrict__ A,
                   const float* __restrict__ B,
                   const int*   __restrict__ obs_raw,
                   const float* __restrict__ pi,
                   float*       __restrict__ out) {
    extern __shared__ float smem[];
    float4* sA      = reinterpret_cast<float4*>(smem);        // [8][S_PITCH]
    float*  s_alpha = smem + 8 * S_PITCH * 4;                 // 4096 floats

    const int tid  = threadIdx.x;
    const int cta  = blockIdx.x;
    const int lane = tid & 31;            // row slot
    const int cg   = tid >> 5;            // warp id = column group, 0..7
    const int gcg  = cta * 8 + cg;
    const int col0 = cta * COLS_PER_CTA;

    const float4*     __restrict__ A4  = reinterpret_cast<const float4*>(A);
    const ulonglong2* __restrict__ A4u = reinterpret_cast<const ulonglong2*>(A);
    const float4*     __restrict__ A4base = A4 + cta * 8;

    // ================= PROLOGUE (all before grid barrier #1) =================

    // obs element-width detect (int64 little-endian: odd dwords are 0)
    int any = 0;
    for (int k = 1 + 2 * tid; k < 1024; k += 2 * NTHR)
        any |= obs_raw[k];
    int is32 = __syncthreads_or(any);

    // A3T transpose: KT*32 = 1024 (slot, col-block) tile tasks over 128 CTAs
    {
        float4 (*tile)[33] = reinterpret_cast<float4(*)[33]>(smem); // scratch
        int tx = tid & 31, ty = tid >> 5;
        for (int task = cta; task < KT * 32; task += NCTA) {
            int s  = task & 31;                        // slot 0..31
            int cb = task >> 5;                        // col block 0..31
            int kk = 32 * (s / 8) + (s % 8) * 3 + 2;   // L2 slots: r=3j+2
            int r0 = 32 * kk, c0 = cb * 32;
            #pragma unroll
            for (int p = 0; p < 4; ++p)
                tile[ty + 8 * p][tx] =
                    A4[(size_t)(r0 + ty + 8 * p) * 1024 + (c0 + tx)];
            __syncthreads();
            #pragma unroll
            for (int p = 0; p < 4; ++p)
                g_A3T[(size_t)(c0 + ty + 8 * p) * T3_ROWS + s * 32 + tx] =
                    tile[tx][ty + 8 * p];
            __syncthreads();
        }
    }

    // Bo gather: 8 timesteps per CTA
    for (int t = cta; t < SEQ_T; t += NCTA) {
        int o = is32 ? obs_raw[t] : obs_raw[2 * t];
        for (int j = tid; j < N_STATES; j += NTHR)
            g_Bo[t * N_STATES + j] = B[j * N_OBS + o];
    }

    // RF tier: k with (k%32)%3 == 0 (44 slots)
    ulonglong2 rA[KR];
    #pragma unroll
    for (int k = 0; k < 128; ++k) {
        int r = k & 31, p = k >> 5;
        if (r % 3 == 0)
            rA[p * 11 + r / 3] = A4u[(size_t)(lane + 32 * k) * 1024 + gcg];
    }

    // SMEM tier (52 slots), sA[cg][slot*32 + row']
    for (int idx = tid; idx < S_ROWS * 8; idx += NTHR) {
        int cgf = idx & 7;
        int rr  = idx >> 3;
        int s = rr >> 5, rp = rr & 31;
        int m = s % 13, p = s / 13;
        int kk = 32 * p + ((m <= 10) ? 3 * m + 1 : (m == 11 ? 26 : 29));
        sA[cgf * S_PITCH + rr] = A4base[(size_t)(32 * kk + rp) * 1024 + cgf];
    }

    const ulonglong2* __restrict__ sAw =
        reinterpret_cast<const ulonglong2*>(sA + cg * S_PITCH);
    const ulonglong2* __restrict__ A3w =
        reinterpret_cast<const ulonglong2*>(g_A3T) + (size_t)gcg * T3_ROWS;

    // alpha0 = pi * Bo[0]
    if (tid < COLS_PER_CTA) {
        int j = col0 + tid;
        int o0 = is32 ? obs_raw[0] : obs_raw[0];
        g_alpha[0][j] = pi[j] * B[j * N_OBS + o0];
    }

    unsigned local_sense = 0;
    grid_barrier(local_sense, gridDim.x);          // barrier #1

    // prefetch ring: period 0's 8 L2 slots (static data, reused every step)
    ulonglong2 pf[8];
    #pragma unroll
    for (int s = 0; s < 8; ++s)
        pf[s] = A3w[s * 32 + lane];

    const unsigned s_alpha_addr = smem_u32(s_alpha);

    // ========================== MAIN SCAN LOOP ==========================
    int cur = 0;
    for (int t = 1; t < SEQ_T; ++t) {
        float4 bo;
        if (lane == 0)
            bo = reinterpret_cast<const float4*>(g_Bo + t * N_STATES)[gcg];

        // stage alpha into smem via cp.async (4 x 16B per thread, one group)
        {
            const float4* asrc = reinterpret_cast<const float4*>(g_alpha[cur]);
            #pragma unroll
            for (int k = 0; k < 4; ++k) {
                unsigned d = s_alpha_addr + 16u * (tid + k * NTHR);
                asm volatile("cp.async.cg.shared.global [%0], [%1], 16;"
                             :: "r"(d), "l"(asrc + tid + k * NTHR) : "memory");
            }
            asm volatile("cp.async.commit_group;" ::: "memory");
            asm volatile("cp.async.wait_group 0;" ::: "memory");
        }
        __syncthreads();

        // dot partials: i = lane + 32k, k ascending 0..127 (order contract)
        ull acc01 = 0ull, acc23 = 0ull;

        #pragma unroll
        for (int k = 0; k < 128; ++k) {
            int r = k & 31, p = k >> 5;
            ull aa = pack2(s_alpha[lane + 32 * k]);
            ulonglong2 v;
            if (r % 3 == 0) {
                v = rA[p * 11 + r / 3];                          // RF
            } else if (r % 3 == 2 && r <= 23) {
                int s = r / 3;                                   // 0..7
                v = pf[s];                                       // L2 (ring)
                int np = (p + 1) & 3;
                pf[s] = A3w[(np * 8 + s) * 32 + lane];           // refill
            } else {
                int m = (r % 3 == 1) ? r / 3 : (r == 26 ? 11 : 12);
                v = sAw[(p * 13 + m) * 32 + lane];               // SMEM
            }
            fma2(acc01, v.x, aa);
            fma2(acc23, v.y, aa);
        }

        // unpack + xor butterfly (== R1's 32-slot tree at lane 0)
        float4 r4;
        asm("mov.b64 {%0, %1}, %2;" : "=f"(r4.x), "=f"(r4.y) : "l"(acc01));
        asm("mov.b64 {%0, %1}, %2;" : "=f"(r4.z), "=f"(r4.w) : "l"(acc23));
        #pragma unroll
        for (int m = 16; m > 0; m >>= 1) {
            r4.x += __shfl_xor_sync(0xffffffffu, r4.x, m);
            r4.y += __shfl_xor_sync(0xffffffffu, r4.y, m);
            r4.z += __shfl_xor_sync(0xffffffffu, r4.z, m);
            r4.w += __shfl_xor_sync(0xffffffffu, r4.w, m);
        }

        if (lane == 0) {
            float4 o4;
            o4.x = r4.x * bo.x; o4.y = r4.y * bo.y;
            o4.z = r4.z * bo.z; o4.w = r4.w * bo.w;
            reinterpret_cast<float4*>(g_alpha[cur ^ 1])[gcg] = o4;
        }

        grid_barrier(local_sense, gridDim.x);      // barriers #2..#1024 (even)
        cur ^= 1;
    }

    // ---- final sum (CTA 0): R1's exact 256-thread tree ----
    if (cta == 0) {
        float* sred = smem;
        float s = 0.f;
        for (int i = tid; i < N_STATES; i += NTHR)
            s += g_alpha[cur][i];
        sred[tid] = s;
        __syncthreads();
        #pragma unroll
        for (int k = NTHR / 2; k > 0; k >>= 1) {
            if (tid < k) sred[tid] += sred[tid + k];
            __syncthreads();
        }
        if (tid == 0) out[0] = sred[0];
    }
}

// ---------------------------------------------------------------------------
extern "C" void kernel_launch(void* const* d_in, const int* in_sizes, int n_in,
                              void* d_out, int out_size) {
    const float* A   = (const float*)d_in[0];
    const float* B   = (const float*)d_in[1];
    const float* pi  = (const float*)d_in[2];
    const int*   obs = (const int*)d_in[3];
    float* out = (float*)d_out;

    cudaFuncSetAttribute(hmm_forward_kernel,
                         cudaFuncAttributeMaxDynamicSharedMemorySize, SMEM_BYTES);

    hmm_forward_kernel<<<NCTA, NTHR, SMEM_BYTES>>>(A, B, obs, pi, out);
}